// round 14
// baseline (speedup 1.0000x reference)
#include <cuda_runtime.h>
#include <cstdint>

// TemporalSpike RLeaky recurrence — R12: byte-LUT + 8 blocks/SM (TILE=2, 10KB smem).
//   rec = spk_prev @ W^T + b_lin  (binary spk -> warp-uniform ballot mask ->
//                                  4 byte lookups in a 128KB __device__ LUT)
//   mem = 0.9*mem + x_t + rec - spk ;  spk = (mem > 1)
// x (16,128,512,32); W (32,32); b (32). Out: spikes then mems, concatenated.
//
// vs R11: staging reshaped to 5 stages x 2KB (TILE=2) = 10KB/block so EIGHT
// blocks fit per SM -> 64 warps/SM (100% occ), full 64K-reg RF use, single
// wave (capacity 1184 > 1024). Lookahead unchanged at 8 t-steps.

#define BB 16
#define TT 128
#define NN 512
#define FF 32
#define ROWS (BB * NN)
#define WPB 8
#define TSTRIDE (NN * FF)          // 16384 floats between t-slices
#define TILE 2
#define NTILE (TT / TILE)          // 64
#define NSTAGE 5
#define XS_TILE (TILE * WPB * FF)  // 512 floats = 2KB per stage

// tabg[p][v][g]: p = byte position (0..3), v = byte value, g = lane.
// Entry = sum of W[g][8p+j] over set bits j of v; bias folded into p==0.
__device__ float tabg[4 * 256 * 32];   // 128 KB

__global__ void build_lut_kernel(const float* __restrict__ W,
                                 const float* __restrict__ b_lin)
{
    const int e = blockIdx.x * 512 + threadIdx.x;   // 0..32767
    const int g = e & 31;
    const int v = (e >> 5) & 255;
    const int p = e >> 13;
    float s = (p == 0) ? b_lin[g] : 0.0f;
    const float* wr = W + g * FF + 8 * p;
    #pragma unroll
    for (int j = 0; j < 8; j++)
        if (v & (1 << j)) s += wr[j];
    tabg[e] = s;
}

__device__ __forceinline__ void cp_async16(uint32_t saddr, const void* gaddr) {
    asm volatile("cp.async.cg.shared.global [%0], [%1], 16;\n"
                 :: "r"(saddr), "l"(gaddr) : "memory");
}
#define CP_COMMIT() asm volatile("cp.async.commit_group;\n" ::: "memory")
#define CP_WAIT(n)  asm volatile("cp.async.wait_group %0;\n" :: "n"(n) : "memory")

__global__ __launch_bounds__(WPB * 32, 8)
void temporal_spike_kernel(const float* __restrict__ x,
                           float* __restrict__ out)
{
    __shared__ float xs[NSTAGE][XS_TILE];     // 10 KB staging, 5 stages

    const int tid  = threadIdx.x;
    const int lane = tid & 31;
    const int w    = tid >> 5;

    const int blk = blockIdx.x;
    const int b   = blk >> 6;                 // 64 blocks per batch
    const int n0  = (blk & 63) * WPB;         // 8 consecutive rows
    const size_t base_blk = ((size_t)b * TT * NN + n0) * FF;

    // Staging role: first 128 threads move 16B each (2 slices x 1KB per tile).
    const int ti = tid >> 6;                  // 0..1 (for tid < 128)
    const int q  = tid & 63;                  // 0..63
    const bool loader = (tid < 128);
    const float* gsrc = x + base_blk + (size_t)ti * TSTRIDE + q * 4;
    const uint32_t sbase = (uint32_t)__cvta_generic_to_shared(&xs[0][0])
                         + (ti * (WPB * FF) + q * 4) * 4;

    // Prologue: tiles 0..3 into stages 0..3 (4 groups in flight).
    #pragma unroll
    for (int k = 0; k < NSTAGE - 1; k++) {
        if (loader)
            cp_async16(sbase + k * (XS_TILE * 4), gsrc + (size_t)k * TILE * TSTRIDE);
        CP_COMMIT();
    }

    float* sp = out + base_blk + w * FF + lane;            // spikes
    float* mp = sp + (size_t)BB * TT * NN * FF;            // mems

    // Per-lane LUT base pointers (byte index warp-uniform -> one coalesced line).
    const float* t0 = tabg + lane;
    const float* t1 = t0 + 1 * 256 * 32;
    const float* t2 = t0 + 2 * 256 * 32;
    const float* t3 = t0 + 3 * 256 * 32;

    float mem = 0.0f, spk = 0.0f;
    unsigned mask = 0u;
    const float* xv = &xs[0][0] + w * FF + lane;

    int buf  = 0;            // buffer holding tile k
    int fbuf = NSTAGE - 1;   // buffer for tile k+NSTAGE-1
    for (int k = 0; k < NTILE; k++) {
        // Keep 4 tiles ahead in flight; then wait for tile k.
        if (k + NSTAGE - 1 < NTILE) {
            if (loader)
                cp_async16(sbase + fbuf * (XS_TILE * 4),
                           gsrc + (size_t)(k + NSTAGE - 1) * TILE * TSTRIDE);
            CP_COMMIT();
            CP_WAIT(4);                        // 5 pending -> tile k complete
        } else if (k == NTILE - 4) {
            CP_WAIT(3);
        } else if (k == NTILE - 3) {
            CP_WAIT(2);
        } else if (k == NTILE - 2) {
            CP_WAIT(1);
        } else {                               // k == NTILE-1
            CP_WAIT(0);
        }
        __syncthreads();   // tile k visible to all warps

        const float* xt = xv + buf * XS_TILE;
        #pragma unroll
        for (int s = 0; s < TILE; s++) {
            const float xval = xt[s * (WPB * FF)];

            const unsigned b0 =  mask        & 255u;
            const unsigned b1 = (mask >>  8) & 255u;
            const unsigned b2 = (mask >> 16) & 255u;
            const unsigned b3 =  mask >> 24;
            const float r0 = __ldg(t0 + b0 * 32);
            const float r1 = __ldg(t1 + b1 * 32);
            const float r2 = __ldg(t2 + b2 * 32);
            const float r3 = __ldg(t3 + b3 * 32);
            const float rec = (r0 + r1) + (r2 + r3);

            mem = fmaf(0.9f, mem, xval + rec - spk);    // THRESH=1
            const bool fire = (mem > 1.0f);
            spk = fire ? 1.0f : 0.0f;
            mask = __ballot_sync(0xffffffffu, fire);

            const size_t off = (size_t)(k * TILE + s) * TSTRIDE;
            __stcs(sp + off, spk);
            __stcs(mp + off, mem);
        }
        __syncthreads();   // release buffer `buf` before it is refilled

        buf  = (buf  == NSTAGE - 1) ? 0 : buf + 1;
        fbuf = (fbuf == NSTAGE - 1) ? 0 : fbuf + 1;
    }
}

extern "C" void kernel_launch(void* const* d_in, const int* in_sizes, int n_in,
                              void* d_out, int out_size)
{
    const float* x     = (const float*)d_in[0];
    const float* W     = (const float*)d_in[1];
    const float* b_lin = (const float*)d_in[2];
    float* out = (float*)d_out;

    build_lut_kernel<<<64, 512>>>(W, b_lin);

    dim3 grid(ROWS / WPB);     // 1024
    dim3 block(WPB * 32);      // 256
    temporal_spike_kernel<<<grid, block>>>(x, out);
}

// round 15
// speedup vs baseline: 1.1113x; 1.1113x over previous
#include <cuda_runtime.h>
#include <cstdint>

// TemporalSpike RLeaky recurrence — R13: R11 kernel + PDL prologue overlap.
//   rec = spk_prev @ W^T + b_lin  (binary spk -> warp-uniform ballot mask ->
//                                  4 byte lookups in a 128KB __device__ LUT)
//   mem = 0.9*mem + x_t + rec - spk ;  spk = (mem > 1)
// x (16,128,512,32); W (32,32); b (32). Out: spikes then mems, concatenated.
//
// Main kernel identical to the 70.8us R11 version (TILE=4, NSTAGE=3, 12KB
// smem, 7 blocks/SM, single wave). New: the LUT-build prologue kernel no
// longer serializes — the main kernel launches with programmatic stream
// serialization (PDL), stages its first x tiles immediately, and executes
// griddepcontrol.wait before the first LUT read.

#define BB 16
#define TT 128
#define NN 512
#define FF 32
#define ROWS (BB * NN)
#define WPB 8
#define TSTRIDE (NN * FF)          // 16384 floats between t-slices
#define TILE 4
#define NTILE (TT / TILE)          // 32
#define NSTAGE 3
#define XS_TILE (TILE * WPB * FF)  // 1024 floats = 4KB per stage

// tabg[p][v][g]: p = byte position (0..3), v = byte value, g = lane.
// Entry = sum of W[g][8p+j] over set bits j of v; bias folded into p==0.
__device__ float tabg[4 * 256 * 32];   // 128 KB

__global__ void build_lut_kernel(const float* __restrict__ W,
                                 const float* __restrict__ b_lin)
{
    const int e = blockIdx.x * 512 + threadIdx.x;   // 0..32767
    const int g = e & 31;
    const int v = (e >> 5) & 255;
    const int p = e >> 13;
    float s = (p == 0) ? b_lin[g] : 0.0f;
    const float* wr = W + g * FF + 8 * p;
    #pragma unroll
    for (int j = 0; j < 8; j++)
        if (v & (1 << j)) s += wr[j];
    tabg[e] = s;
    // Signal dependent grid may launch (memory ordering of tabg writes vs the
    // dependent grid's griddepcontrol.wait is guaranteed by PDL semantics).
    asm volatile("griddepcontrol.launch_dependents;" ::: "memory");
}

__device__ __forceinline__ void cp_async16(uint32_t saddr, const void* gaddr) {
    asm volatile("cp.async.cg.shared.global [%0], [%1], 16;\n"
                 :: "r"(saddr), "l"(gaddr) : "memory");
}
#define CP_COMMIT() asm volatile("cp.async.commit_group;\n" ::: "memory")
#define CP_WAIT(n)  asm volatile("cp.async.wait_group %0;\n" :: "n"(n) : "memory")

__global__ __launch_bounds__(WPB * 32, 7)
void temporal_spike_kernel(const float* __restrict__ x,
                           float* __restrict__ out)
{
    __shared__ float xs[NSTAGE][XS_TILE];     // 12 KB staging, 3 stages

    const int tid  = threadIdx.x;
    const int lane = tid & 31;
    const int w    = tid >> 5;

    const int blk = blockIdx.x;
    const int b   = blk >> 6;                 // 64 blocks per batch
    const int n0  = (blk & 63) * WPB;         // 8 consecutive rows
    const size_t base_blk = ((size_t)b * TT * NN + n0) * FF;

    // Staging role: thread -> (t-slice in tile, 16B chunk within the 1KB slice)
    const int ti = tid >> 6;                  // 0..3
    const int q  = tid & 63;                  // 0..63
    const float* gsrc = x + base_blk + (size_t)ti * TSTRIDE + q * 4;
    const uint32_t sbase = (uint32_t)__cvta_generic_to_shared(&xs[0][0])
                         + (ti * (WPB * FF) + q * 4) * 4;

    // Stage tiles 0..1 while the LUT-build grid may still be draining.
    #pragma unroll
    for (int k = 0; k < NSTAGE - 1; k++) {
        cp_async16(sbase + k * (XS_TILE * 4), gsrc + (size_t)k * TILE * TSTRIDE);
        CP_COMMIT();
    }

    float* sp = out + base_blk + w * FF + lane;            // spikes
    float* mp = sp + (size_t)BB * TT * NN * FF;            // mems

    // Per-lane LUT base pointers (byte index warp-uniform -> one coalesced line).
    const float* t0 = tabg + lane;
    const float* t1 = t0 + 1 * 256 * 32;
    const float* t2 = t0 + 2 * 256 * 32;
    const float* t3 = t0 + 3 * 256 * 32;

    float mem = 0.0f, spk = 0.0f;
    unsigned mask = 0u;
    const float* xv = &xs[0][0] + w * FF + lane;

    // PDL: ensure the predecessor grid (LUT build) has completed before the
    // first tabg read below. Executed by every thread.
    asm volatile("griddepcontrol.wait;" ::: "memory");

    int buf  = 0;            // buffer holding tile k
    int fbuf = NSTAGE - 1;   // buffer for tile k+NSTAGE-1
    for (int k = 0; k < NTILE; k++) {
        // Keep 2 tiles ahead in flight; then wait for tile k.
        if (k + NSTAGE - 1 < NTILE) {
            cp_async16(sbase + fbuf * (XS_TILE * 4),
                       gsrc + (size_t)(k + NSTAGE - 1) * TILE * TSTRIDE);
            CP_COMMIT();
            CP_WAIT(2);                        // 3 pending -> tile k complete
        } else if (k == NTILE - 2) {
            CP_WAIT(1);
        } else {                               // k == NTILE-1
            CP_WAIT(0);
        }
        __syncthreads();   // tile k visible to all warps

        const float* xt = xv + buf * XS_TILE;
        #pragma unroll
        for (int s = 0; s < TILE; s++) {
            const float xval = xt[s * (WPB * FF)];

            const unsigned b0 =  mask        & 255u;
            const unsigned b1 = (mask >>  8) & 255u;
            const unsigned b2 = (mask >> 16) & 255u;
            const unsigned b3 =  mask >> 24;
            const float r0 = __ldg(t0 + b0 * 32);
            const float r1 = __ldg(t1 + b1 * 32);
            const float r2 = __ldg(t2 + b2 * 32);
            const float r3 = __ldg(t3 + b3 * 32);
            const float rec = (r0 + r1) + (r2 + r3);

            mem = fmaf(0.9f, mem, xval + rec - spk);    // THRESH=1
            const bool fire = (mem > 1.0f);
            spk = fire ? 1.0f : 0.0f;
            mask = __ballot_sync(0xffffffffu, fire);

            const size_t off = (size_t)(k * TILE + s) * TSTRIDE;
            __stcs(sp + off, spk);
            __stcs(mp + off, mem);
        }
        __syncthreads();   // release buffer `buf` before it is refilled

        buf  = (buf  == NSTAGE - 1) ? 0 : buf + 1;
        fbuf = (fbuf == NSTAGE - 1) ? 0 : fbuf + 1;
    }
}

extern "C" void kernel_launch(void* const* d_in, const int* in_sizes, int n_in,
                              void* d_out, int out_size)
{
    const float* x     = (const float*)d_in[0];
    const float* W     = (const float*)d_in[1];
    const float* b_lin = (const float*)d_in[2];
    float* out = (float*)d_out;

    build_lut_kernel<<<64, 512>>>(W, b_lin);

    // Main kernel with programmatic dependent launch: overlaps its launch and
    // cp.async staging prologue with the LUT-build drain; griddepcontrol.wait
    // inside the kernel orders the first tabg read.
    cudaLaunchConfig_t cfg = {};
    cfg.gridDim  = dim3(ROWS / WPB);   // 1024
    cfg.blockDim = dim3(WPB * 32);     // 256
    cfg.dynamicSmemBytes = 0;
    cfg.stream = 0;
    cudaLaunchAttribute attrs[1];
    attrs[0].id = cudaLaunchAttributeProgrammaticStreamSerialization;
    attrs[0].val.programmaticStreamSerializationAllowed = 1;
    cfg.attrs = attrs;
    cfg.numAttrs = 1;
    cudaLaunchKernelEx(&cfg, temporal_spike_kernel, x, out);
}